// round 6
// baseline (speedup 1.0000x reference)
#include <cuda_runtime.h>
#include <cuda_bf16.h>
#include <cstddef>

#define Hn 1024
#define Bn 128
#define Tn 400
#define Sn 64
#define Cn 8
#define NEXC 819

// ---- scratch (static __device__ globals: the sanctioned no-alloc scratch) ----
__device__ float g_Wt[Hn * Hn];               // W^T: Wt[j*H + i] = sign_i * relu(w_rec[i,j]) * (i!=j)
__device__ float g_drive[(size_t)Tn * Bn * Hn]; // [t][b][h] feedforward drive (210 MB)
__device__ float g_h[Bn * Hn];
__device__ float g_sx[Bn * Hn];
__device__ float g_su[Bn * Hn];
__device__ float g_hp[Bn * Hn];               // h_post for the *next* step's GEMM

// ---------------------------------------------------------------------------
// Prep: effective recurrent weights, transposed for coalesced K-reads.
// out[b,j] = sum_i hp[b,i] * W[i,j]  ->  Wt[j][i]
// ---------------------------------------------------------------------------
__global__ void prep_W(const float* __restrict__ w_rec) {
    int o = blockIdx.x * blockDim.x + threadIdx.x;   // o = j*H + i
    int j = o >> 10;
    int i = o & 1023;
    float v = fmaxf(w_rec[i * Hn + j], 0.f);
    if (i == j) v = 0.f;
    g_Wt[o] = (i < NEXC) ? v : -v;
}

__global__ void init_state() {
    int idx = blockIdx.x * blockDim.x + threadIdx.x;
    g_h[idx]  = 0.f;
    g_hp[idx] = 0.f;                       // hp for step 0 is 0 (h0 = 0)
    g_sx[idx] = 1.f;                       // fixed point of first STP update
    g_su[idx] = (idx & 1) ? 0.15f : 0.45f; // U (odd=fast/facilitating)
}

// ---------------------------------------------------------------------------
// Drive precompute: drive[t,b,h] = stim[b,t,:]·w_in[h,:] + ctx[b,t,:]·w_ctx[h,:]
// GEMM K=72, tiles 64(h) x 64(b), 4x4 microtile, 256 threads. Grid (T,16,2).
// ---------------------------------------------------------------------------
__global__ __launch_bounds__(256) void drive_kernel(
    const float* __restrict__ stim, const float* __restrict__ ctx,
    const float* __restrict__ w_in, const float* __restrict__ w_ctx)
{
    __shared__ __align__(16) float ws[72][68];  // [k][h_local]
    __shared__ __align__(16) float xs[72][68];  // [k][b_local]
    const int t  = blockIdx.x;
    const int h0 = blockIdx.y * 64;
    const int b0 = blockIdx.z * 64;
    const int tid = threadIdx.x;

    {   // stage stimulus rows + w_in rows (coalesced over s)
        int s = tid & 63, l0 = tid >> 6;           // l0 in 0..3
        for (int l = l0; l < 64; l += 4) {
            ws[s][l] = w_in[(h0 + l) * Sn + s];
            xs[s][l] = stim[((size_t)(b0 + l) * Tn + t) * Sn + s];
        }
        int c = tid & 7, m0 = tid >> 3;            // m0 in 0..31
        for (int l = m0; l < 64; l += 32) {
            ws[64 + c][l] = w_ctx[(h0 + l) * Cn + c];
            xs[64 + c][l] = ctx[((size_t)(b0 + l) * Tn + t) * Cn + c];
        }
    }
    __syncthreads();

    const int txh = tid & 15;   // h micro group
    const int tyb = tid >> 4;   // b micro group
    float acc[4][4] = {};       // acc[bb][hh]
    #pragma unroll 8
    for (int k = 0; k < 72; k++) {
        float4 a = *(const float4*)&ws[k][txh * 4];
        float4 x = *(const float4*)&xs[k][tyb * 4];
        acc[0][0] += x.x * a.x; acc[0][1] += x.x * a.y; acc[0][2] += x.x * a.z; acc[0][3] += x.x * a.w;
        acc[1][0] += x.y * a.x; acc[1][1] += x.y * a.y; acc[1][2] += x.y * a.z; acc[1][3] += x.y * a.w;
        acc[2][0] += x.z * a.x; acc[2][1] += x.z * a.y; acc[2][2] += x.z * a.z; acc[2][3] += x.z * a.w;
        acc[3][0] += x.w * a.x; acc[3][1] += x.w * a.y; acc[3][2] += x.w * a.z; acc[3][3] += x.w * a.w;
    }

    const size_t base = (size_t)t * Bn * Hn;
    #pragma unroll
    for (int bb = 0; bb < 4; bb++) {
        int b = b0 + tyb * 4 + bb;
        float4 v = make_float4(acc[bb][0], acc[bb][1], acc[bb][2], acc[bb][3]);
        *(float4*)&g_drive[base + (size_t)b * Hn + h0 + txh * 4] = v;
    }
}

// ---------------------------------------------------------------------------
// One timestep: GEMM out[b,j] = hp·Wt[j] with fused epilogue:
//   h_new = relu(0.8*h + 0.2*(drive + rec + b_rec) + 0.05*noise)
//   then compute NEXT step's sx/su/h_post in-place.
// 32(b) x 32(j) block tile, 2x2 microtile, 256 threads, grid (32,4)=128 blocks.
// Wt (4MB) stays L2-resident across all 400 launches.
// ---------------------------------------------------------------------------
__global__ __launch_bounds__(256) void step_kernel(
    const float* __restrict__ noise, const float* __restrict__ b_rec,
    float* __restrict__ acts, int t)
{
    __shared__ __align__(16) float As[32][34];  // [k][b]
    __shared__ __align__(16) float Bs[32][34];  // [k][j]
    const int tid = threadIdx.x;
    const int tx = tid & 15;     // j micro
    const int ty = tid >> 4;     // b micro
    const int jt = blockIdx.x * 32;
    const int bt = blockIdx.y * 32;
    const int kl = tid & 31;     // k lane within tile
    const int rl = tid >> 5;     // 0..7 row group

    const float* hpBase = g_hp + (size_t)(bt) * Hn + kl;
    const float* wBase  = g_Wt + (size_t)(jt) * Hn + kl;

    float a00 = 0.f, a01 = 0.f, a10 = 0.f, a11 = 0.f;
    float pa[4], pb[4];
    #pragma unroll
    for (int r = 0; r < 4; r++) {
        pa[r] = hpBase[(rl + 8 * r) * Hn];
        pb[r] = wBase[(rl + 8 * r) * Hn];
    }

    for (int k0 = 0; k0 < Hn; k0 += 32) {
        #pragma unroll
        for (int r = 0; r < 4; r++) {
            As[kl][rl + 8 * r] = pa[r];
            Bs[kl][rl + 8 * r] = pb[r];
        }
        __syncthreads();
        if (k0 + 32 < Hn) {
            #pragma unroll
            for (int r = 0; r < 4; r++) {
                pa[r] = hpBase[(rl + 8 * r) * Hn + k0 + 32];
                pb[r] = wBase[(rl + 8 * r) * Hn + k0 + 32];
            }
        }
        #pragma unroll
        for (int kk = 0; kk < 32; kk++) {
            float2 av = *(const float2*)&As[kk][2 * ty];
            float2 bv = *(const float2*)&Bs[kk][2 * tx];
            a00 += av.x * bv.x; a01 += av.x * bv.y;
            a10 += av.y * bv.x; a11 += av.y * bv.y;
        }
        __syncthreads();
    }

    float accv[2][2] = {{a00, a01}, {a10, a11}};
    const size_t tbase = (size_t)t * Bn * Hn;
    const float ax_even = (float)(20.0 / 1500.0);

    #pragma unroll
    for (int i = 0; i < 2; i++) {
        int b = bt + 2 * ty + i;
        #pragma unroll
        for (int jj2 = 0; jj2 < 2; jj2++) {
            int jj  = jt + 2 * tx + jj2;
            int idx = b * Hn + jj;
            float d    = g_drive[tbase + idx];
            float nz   = noise[tbase + idx];
            float hold = g_h[idx];
            float hnew = 0.8f * hold + 0.2f * (d + accv[i][jj2] + b_rec[jj]) + 0.05f * nz;
            hnew = fmaxf(hnew, 0.f);
            acts[((size_t)b * Tn + t) * Hn + jj] = hnew;
            g_h[idx] = hnew;

            // STP update for next step (uses sx_t, su_t, h_t)
            float sx = g_sx[idx], su = g_su[idx];
            bool odd = (jj & 1);
            float ax = odd ? 0.1f : ax_even;
            float U  = odd ? 0.15f : 0.45f;
            float sxn = sx + ax * (1.f - sx) - 0.02f * su * sx * hnew;
            sxn = fminf(fmaxf(sxn, 0.f), 1.f);
            float sun = su + ax * (U - su) + 0.02f * U * (1.f - su) * hnew;
            sun = fminf(fmaxf(sun, 0.f), 1.f);
            g_sx[idx] = sxn;
            g_su[idx] = sun;
            g_hp[idx] = sun * sxn * hnew;
        }
    }
}

// ---------------------------------------------------------------------------
// Heads: outputs = acts·w_out^T + b_out ; z = acts·c1_w^T + c1_b ; p = z·c2_w^T + c2_b
// One block per (t,b); 9 dot products of length 1024, block-reduced.
// ---------------------------------------------------------------------------
__global__ __launch_bounds__(128) void head_kernel(
    const float* __restrict__ acts, const float* __restrict__ w_out,
    const float* __restrict__ b_out, const float* __restrict__ c1_w,
    const float* __restrict__ c1_b, const float* __restrict__ c2_w,
    const float* __restrict__ c2_b, float* __restrict__ outputs,
    float* __restrict__ p)
{
    const int t = blockIdx.x, b = blockIdx.y;
    const int tid = threadIdx.x;
    float s[9] = {};
    const float* arow = acts + ((size_t)b * Tn + t) * Hn;
    for (int h = tid; h < Hn; h += 128) {
        float a = arow[h];
        #pragma unroll
        for (int o = 0; o < 3; o++) s[o] = fmaf(a, w_out[o * Hn + h], s[o]);
        #pragma unroll
        for (int m = 0; m < 6; m++) s[3 + m] = fmaf(a, c1_w[m * Hn + h], s[3 + m]);
    }
    __shared__ float red[9][128];
    #pragma unroll
    for (int q = 0; q < 9; q++) red[q][tid] = s[q];
    __syncthreads();
    for (int st = 64; st > 0; st >>= 1) {
        if (tid < st) {
            #pragma unroll
            for (int q = 0; q < 9; q++) red[q][tid] += red[q][tid + st];
        }
        __syncthreads();
    }
    if (tid == 0) {
        size_t ob = ((size_t)b * Tn + t) * 3;
        #pragma unroll
        for (int o = 0; o < 3; o++) outputs[ob + o] = red[o][0] + b_out[o];
        float z[6];
        #pragma unroll
        for (int m = 0; m < 6; m++) z[m] = red[3 + m][0] + c1_b[m];
        size_t pb = ((size_t)b * Tn + t) * 24;
        #pragma unroll
        for (int j = 0; j < 3; j++)
            #pragma unroll
            for (int o = 0; o < 8; o++)
                p[pb + j * 8 + o] = c2_b[j * 8 + o]
                                  + z[j * 2 + 0] * c2_w[j * 16 + o * 2 + 0]
                                  + z[j * 2 + 1] * c2_w[j * 16 + o * 2 + 1];
    }
}

// ---------------------------------------------------------------------------
extern "C" void kernel_launch(void* const* d_in, const int* in_sizes, int n_in,
                              void* d_out, int out_size)
{
    (void)in_sizes; (void)n_in; (void)out_size;
    const float* stim  = (const float*)d_in[0];
    const float* ctx   = (const float*)d_in[1];
    const float* w_rec = (const float*)d_in[2];
    const float* b_rec = (const float*)d_in[3];
    const float* w_in  = (const float*)d_in[4];
    const float* w_ctx = (const float*)d_in[5];
    const float* w_out = (const float*)d_in[6];
    const float* b_out = (const float*)d_in[7];
    const float* c1_w  = (const float*)d_in[8];
    const float* c1_b  = (const float*)d_in[9];
    const float* c2_w  = (const float*)d_in[10];
    const float* c2_b  = (const float*)d_in[11];
    const float* noise = (const float*)d_in[12];

    float* out      = (float*)d_out;
    float* outputs  = out;                                         // [B,T,3]
    float* acts     = out + (size_t)Bn * Tn * 3;                   // [B,T,H]
    float* p        = acts + (size_t)Bn * Tn * Hn;                 // [B,T,3,8]

    prep_W<<<(Hn * Hn) / 256, 256>>>(w_rec);
    init_state<<<(Bn * Hn) / 256, 256>>>();
    drive_kernel<<<dim3(Tn, Hn / 64, Bn / 64), 256>>>(stim, ctx, w_in, w_ctx);

    for (int t = 0; t < Tn; t++)
        step_kernel<<<dim3(Hn / 32, Bn / 32), 256>>>(noise, b_rec, acts, t);

    head_kernel<<<dim3(Tn, Bn), 128>>>(acts, w_out, b_out, c1_w, c1_b,
                                       c2_w, c2_b, outputs, p);
}

// round 8
// speedup vs baseline: 1.4611x; 1.4611x over previous
#include <cuda_runtime.h>
#include <cuda_bf16.h>
#include <cstddef>

#define Hn 1024
#define Bn 128
#define Tn 400
#define Sn 64
#define Cn 8
#define NEXC 819

// persistent-kernel config
#define NB 128      // blocks (all co-resident: 1/SM, <=148)
#define NT 256      // threads per block
#define KSPLIT 8
#define KS 128      // Hn / KSPLIT
#define TJ 128      // j-tile
#define TB 64       // b-tile

// ---- scratch (__device__ globals: sanctioned no-alloc scratch) ----
__device__ float g_W[Hn * Hn];                   // W[i][j] = sign_i*relu(w_rec[i,j])*(i!=j)
__device__ float g_drive[(size_t)Tn * Bn * Hn];  // 0.2*(ff drive + b_rec), [t][b][h]
__device__ float g_hp[2][Hn * Bn];               // h_post, TRANSPOSED [parity][i][b]
__device__ float g_part[KSPLIT][Bn * Hn];        // split-K partials [ks][b][j]
__device__ unsigned g_bar_count;
__device__ unsigned g_bar_gen;

// ---------------------------------------------------------------------------
__global__ void prep_W(const float* __restrict__ w_rec) {
    int o = blockIdx.x * blockDim.x + threadIdx.x;   // o = i*H + j
    int i = o >> 10;
    int j = o & 1023;
    float v = fmaxf(w_rec[o], 0.f);
    if (i == j) v = 0.f;
    g_W[o] = (i < NEXC) ? v : -v;
}

__global__ void init_state() {
    int idx = blockIdx.x * blockDim.x + threadIdx.x;
    if (idx < Hn * Bn) g_hp[0][idx] = 0.f;           // h0 = 0 -> hp0 = 0
    if (idx == 0) { g_bar_count = 0; g_bar_gen = 0; }
}

// ---------------------------------------------------------------------------
// Drive precompute: drive[t,b,h] = 0.2*(stim·w_in + ctx·w_ctx + b_rec)
// ---------------------------------------------------------------------------
__global__ __launch_bounds__(256) void drive_kernel(
    const float* __restrict__ stim, const float* __restrict__ ctx,
    const float* __restrict__ w_in, const float* __restrict__ w_ctx,
    const float* __restrict__ b_rec)
{
    __shared__ __align__(16) float ws[72][68];  // [k][h_local]
    __shared__ __align__(16) float xs[72][68];  // [k][b_local]
    const int t  = blockIdx.x;
    const int h0 = blockIdx.y * 64;
    const int b0 = blockIdx.z * 64;
    const int tid = threadIdx.x;

    {
        int s = tid & 63, l0 = tid >> 6;
        for (int l = l0; l < 64; l += 4) {
            ws[s][l] = w_in[(h0 + l) * Sn + s];
            xs[s][l] = stim[((size_t)(b0 + l) * Tn + t) * Sn + s];
        }
        int c = tid & 7, m0 = tid >> 3;
        for (int l = m0; l < 64; l += 32) {
            ws[64 + c][l] = w_ctx[(h0 + l) * Cn + c];
            xs[64 + c][l] = ctx[((size_t)(b0 + l) * Tn + t) * Cn + c];
        }
    }
    __syncthreads();

    const int txh = tid & 15;
    const int tyb = tid >> 4;
    float acc[4][4] = {};
    #pragma unroll 8
    for (int k = 0; k < 72; k++) {
        float4 a = *(const float4*)&ws[k][txh * 4];
        float4 x = *(const float4*)&xs[k][tyb * 4];
        acc[0][0] += x.x * a.x; acc[0][1] += x.x * a.y; acc[0][2] += x.x * a.z; acc[0][3] += x.x * a.w;
        acc[1][0] += x.y * a.x; acc[1][1] += x.y * a.y; acc[1][2] += x.y * a.z; acc[1][3] += x.y * a.w;
        acc[2][0] += x.z * a.x; acc[2][1] += x.z * a.y; acc[2][2] += x.z * a.z; acc[2][3] += x.z * a.w;
        acc[3][0] += x.w * a.x; acc[3][1] += x.w * a.y; acc[3][2] += x.w * a.z; acc[3][3] += x.w * a.w;
    }

    float4 br = *(const float4*)&b_rec[h0 + txh * 4];
    const size_t base = (size_t)t * Bn * Hn;
    #pragma unroll
    for (int bb = 0; bb < 4; bb++) {
        int b = b0 + tyb * 4 + bb;
        float4 v = make_float4(0.2f * (acc[bb][0] + br.x),
                               0.2f * (acc[bb][1] + br.y),
                               0.2f * (acc[bb][2] + br.z),
                               0.2f * (acc[bb][3] + br.w));
        *(float4*)&g_drive[base + (size_t)b * Hn + h0 + txh * 4] = v;
    }
}

// ---------------------------------------------------------------------------
// Manual grid barrier (all NB blocks co-resident)
// ---------------------------------------------------------------------------
__device__ __forceinline__ void grid_bar(unsigned& genl) {
    __syncthreads();
    if (threadIdx.x == 0) {
        __threadfence();                       // make this block's STGs visible
        unsigned g = genl;
        unsigned old = atomicAdd(&g_bar_count, 1);
        if (old == NB - 1) {
            g_bar_count = 0;
            __threadfence();
            atomicAdd(&g_bar_gen, 1);
        } else {
            volatile unsigned* pg = &g_bar_gen;
            while (*pg <= g) { }
        }
        __threadfence();
        genl = g + 1;
    }
    __syncthreads();
}

// ---------------------------------------------------------------------------
// Persistent kernel: all 400 steps. Per step:
//   [GEMM partial: 128j x 64b x 128k slice, W resident in smem] -> partials
//   grid_bar
//   [epilogue: each thread owns 4 fixed (b,j); h/sx/su in registers]
//   grid_bar
// ---------------------------------------------------------------------------
__global__ __launch_bounds__(NT, 1) void rnn_persistent(
    const float* __restrict__ noise, float* __restrict__ acts)
{
    extern __shared__ float sm[];
    float* Ws = sm;                  // [KS][TJ]  64KB, resident across steps
    float* Hs = sm + KS * TJ;        // [KS][TB]  32KB, restaged each step

    const int tid = threadIdx.x;
    const int bid = blockIdx.x;
    const int tile = bid >> 3;                 // 16 tiles
    const int ks   = bid & 7;
    const int j0 = (tile >> 1) * TJ;
    const int b0 = (tile & 1) * TB;
    const int k0 = ks * KS;

    // load this block's W slice once (no W traffic afterwards)
    for (int i = tid; i < KS * TJ / 4; i += NT) {
        int k = i >> 5, j4 = i & 31;
        *(float4*)&Ws[k * TJ + j4 * 4] =
            *(const float4*)&g_W[(size_t)(k0 + k) * Hn + j0 + j4 * 4];
    }

    // epilogue ownership: 4 consecutive j at fixed b, state in registers
    const int gtid = bid * NT + tid;
    const int e0 = gtid * 4;
    const int eb = e0 >> 10;
    const int ej = e0 & 1023;
    float hr[4]  = {0.f, 0.f, 0.f, 0.f};
    float sxr[4] = {1.f, 1.f, 1.f, 1.f};
    float sur[4] = {0.45f, 0.15f, 0.45f, 0.15f};
    const float axc[4] = {20.f/1500.f, 0.1f, 20.f/1500.f, 0.1f};
    const float Uc[4]  = {0.45f, 0.15f, 0.45f, 0.15f};

    const int tx = tid & 15;     // j micro group (8 wide)
    const int ty = tid >> 4;     // b micro group (4 wide)

    unsigned genl = 0;
    __syncthreads();

    for (int t = 0; t < Tn; t++) {
        const int p = t & 1;

        // stage hp slice [k0..k0+127][b0..b0+63] (coalesced, L2-fresh)
        for (int i = tid; i < KS * TB / 4; i += NT) {
            int k = i >> 4, b4 = i & 15;
            float4 v = __ldcg((const float4*)&g_hp[p][(size_t)(k0 + k) * Bn + b0 + b4 * 4]);
            *(float4*)&Hs[k * TB + b4 * 4] = v;
        }
        __syncthreads();

        // ---- GEMM partial: acc[4b][8j] ----
        float acc[4][8];
        #pragma unroll
        for (int a = 0; a < 4; a++)
            #pragma unroll
            for (int c = 0; c < 8; c++) acc[a][c] = 0.f;

        #pragma unroll 4
        for (int k = 0; k < KS; k++) {
            float4 av = *(const float4*)&Hs[k * TB + ty * 4];
            float4 w0 = *(const float4*)&Ws[k * TJ + tx * 8];
            float4 w1 = *(const float4*)&Ws[k * TJ + tx * 8 + 4];
            float am[4] = {av.x, av.y, av.z, av.w};
            float wm[8] = {w0.x, w0.y, w0.z, w0.w, w1.x, w1.y, w1.z, w1.w};
            #pragma unroll
            for (int a = 0; a < 4; a++)
                #pragma unroll
                for (int c = 0; c < 8; c++)
                    acc[a][c] = fmaf(am[a], wm[c], acc[a][c]);
        }

        #pragma unroll
        for (int a = 0; a < 4; a++) {
            int b = b0 + ty * 4 + a;
            float* dst = &g_part[ks][(size_t)b * Hn + j0 + tx * 8];
            *(float4*)dst       = make_float4(acc[a][0], acc[a][1], acc[a][2], acc[a][3]);
            *(float4*)(dst + 4) = make_float4(acc[a][4], acc[a][5], acc[a][6], acc[a][7]);
        }

        grid_bar(genl);

        // ---- epilogue: reduce split-K, neuron + STP update ----
        {
            const size_t pi = (size_t)eb * Hn + ej;
            float4 r = __ldcg((const float4*)&g_part[0][pi]);
            #pragma unroll
            for (int s = 1; s < KSPLIT; s++) {
                float4 q = __ldcg((const float4*)&g_part[s][pi]);
                r.x += q.x; r.y += q.y; r.z += q.z; r.w += q.w;
            }
            const size_t ti = ((size_t)t * Bn + eb) * Hn + ej;
            float4 d  = __ldcs((const float4*)&g_drive[ti]);
            float4 nz = __ldcs((const float4*)&noise[ti]);

            float rv[4] = {r.x, r.y, r.z, r.w};
            float dv[4] = {d.x, d.y, d.z, d.w};
            float nv[4] = {nz.x, nz.y, nz.z, nz.w};
            float hn[4];
            #pragma unroll
            for (int u = 0; u < 4; u++) {
                float h = fmaxf(0.8f * hr[u] + dv[u] + 0.2f * rv[u] + 0.05f * nv[u], 0.f);
                hn[u] = h;
                float sx = sxr[u], su = sur[u];
                float ax = axc[u], U = Uc[u];
                float sxn = sx + ax * (1.f - sx) - 0.02f * su * sx * h;
                sxn = fminf(fmaxf(sxn, 0.f), 1.f);
                float sun = su + ax * (U - su) + 0.02f * U * (1.f - su) * h;
                sun = fminf(fmaxf(sun, 0.f), 1.f);
                hr[u] = h; sxr[u] = sxn; sur[u] = sun;
                g_hp[p ^ 1][(size_t)(ej + u) * Bn + eb] = sun * sxn * h;
            }
            *(float4*)&acts[((size_t)eb * Tn + t) * Hn + ej] =
                make_float4(hn[0], hn[1], hn[2], hn[3]);
        }

        grid_bar(genl);
    }
}

// ---------------------------------------------------------------------------
__global__ __launch_bounds__(128) void head_kernel(
    const float* __restrict__ acts, const float* __restrict__ w_out,
    const float* __restrict__ b_out, const float* __restrict__ c1_w,
    const float* __restrict__ c1_b, const float* __restrict__ c2_w,
    const float* __restrict__ c2_b, float* __restrict__ outputs,
    float* __restrict__ p)
{
    const int t = blockIdx.x, b = blockIdx.y;
    const int tid = threadIdx.x;
    float s[9] = {};
    const float* arow = acts + ((size_t)b * Tn + t) * Hn;
    for (int h = tid; h < Hn; h += 128) {
        float a = arow[h];
        #pragma unroll
        for (int o = 0; o < 3; o++) s[o] = fmaf(a, w_out[o * Hn + h], s[o]);
        #pragma unroll
        for (int m = 0; m < 6; m++) s[3 + m] = fmaf(a, c1_w[m * Hn + h], s[3 + m]);
    }
    __shared__ float red[9][128];
    #pragma unroll
    for (int q = 0; q < 9; q++) red[q][tid] = s[q];
    __syncthreads();
    for (int st = 64; st > 0; st >>= 1) {
        if (tid < st) {
            #pragma unroll
            for (int q = 0; q < 9; q++) red[q][tid] += red[q][tid + st];
        }
        __syncthreads();
    }
    if (tid == 0) {
        size_t ob = ((size_t)b * Tn + t) * 3;
        #pragma unroll
        for (int o = 0; o < 3; o++) outputs[ob + o] = red[o][0] + b_out[o];
        float z[6];
        #pragma unroll
        for (int m = 0; m < 6; m++) z[m] = red[3 + m][0] + c1_b[m];
        size_t pb = ((size_t)b * Tn + t) * 24;
        #pragma unroll
        for (int j = 0; j < 3; j++)
            #pragma unroll
            for (int o = 0; o < 8; o++)
                p[pb + j * 8 + o] = c2_b[j * 8 + o]
                                  + z[j * 2 + 0] * c2_w[j * 16 + o * 2 + 0]
                                  + z[j * 2 + 1] * c2_w[j * 16 + o * 2 + 1];
    }
}

// ---------------------------------------------------------------------------
extern "C" void kernel_launch(void* const* d_in, const int* in_sizes, int n_in,
                              void* d_out, int out_size)
{
    (void)in_sizes; (void)n_in; (void)out_size;
    const float* stim  = (const float*)d_in[0];
    const float* ctx   = (const float*)d_in[1];
    const float* w_rec = (const float*)d_in[2];
    const float* b_rec = (const float*)d_in[3];
    const float* w_in  = (const float*)d_in[4];
    const float* w_ctx = (const float*)d_in[5];
    const float* w_out = (const float*)d_in[6];
    const float* b_out = (const float*)d_in[7];
    const float* c1_w  = (const float*)d_in[8];
    const float* c1_b  = (const float*)d_in[9];
    const float* c2_w  = (const float*)d_in[10];
    const float* c2_b  = (const float*)d_in[11];
    const float* noise = (const float*)d_in[12];

    float* out      = (float*)d_out;
    float* outputs  = out;                              // [B,T,3]
    float* acts     = out + (size_t)Bn * Tn * 3;        // [B,T,H]
    float* p        = acts + (size_t)Bn * Tn * Hn;      // [B,T,3,8]

    static bool attr_set = false;
    if (!attr_set) {
        cudaFuncSetAttribute(rnn_persistent,
                             cudaFuncAttributeMaxDynamicSharedMemorySize,
                             (KS * TJ + KS * TB) * (int)sizeof(float));
        attr_set = true;
    }

    prep_W<<<(Hn * Hn) / 256, 256>>>(w_rec);
    init_state<<<(Bn * Hn) / 256, 256>>>();
    drive_kernel<<<dim3(Tn, Hn / 64, Bn / 64), 256>>>(stim, ctx, w_in, w_ctx, b_rec);

    rnn_persistent<<<NB, NT, (KS * TJ + KS * TB) * sizeof(float)>>>(noise, acts);

    head_kernel<<<dim3(Tn, Bn), 128>>>(acts, w_out, b_out, c1_w, c1_b,
                                       c2_w, c2_b, outputs, p);
}

// round 9
// speedup vs baseline: 2.3153x; 1.5846x over previous
#include <cuda_runtime.h>
#include <cuda_bf16.h>
#include <cstddef>

#define Hn 1024
#define Bn 128
#define Tn 400
#define Sn 64
#define Cn 8
#define NEXC 819

// persistent-kernel config
#define NB 128      // blocks (all co-resident: 1/SM)
#define NT 256      // threads per block
#define KSPLIT 8
#define KS 128      // Hn / KSPLIT
#define TJ 128      // j-tile
#define TB 64       // b-tile
#define ROWW 66     // padded smem row width in 32-bit words (64 data + 2 pad)

// ---- scratch (__device__ globals) ----
__device__ unsigned g_WHt[Hn * Hn / 2];          // bf16 hi of W^T: [j][i], packed pairs
__device__ unsigned g_WLt[Hn * Hn / 2];          // bf16 lo of W^T
__device__ float    g_drive[(size_t)Tn * Bn * Hn];
__device__ unsigned g_hpHu[2][Bn * Hn / 2];      // h_post bf16 hi, [parity][b][i] packed
__device__ unsigned g_hpLu[2][Bn * Hn / 2];      // h_post bf16 lo
__device__ float    g_part[KSPLIT][Bn * Hn];     // split-K partials [ks][b][j]
__device__ unsigned g_bar_count;
__device__ unsigned g_bar_gen;

// ---------------------------------------------------------------------------
__global__ void prep_W(const float* __restrict__ w_rec) {
    int o = blockIdx.x * blockDim.x + threadIdx.x;   // o = i*H + j
    int i = o >> 10;
    int j = o & 1023;
    float v = fmaxf(w_rec[o], 0.f);
    if (i == j) v = 0.f;
    v = (i < NEXC) ? v : -v;
    __nv_bfloat16 hi = __float2bfloat16_rn(v);
    float hif = __bfloat162float(hi);
    __nv_bfloat16 lo = __float2bfloat16_rn(v - hif);
    // transposed scatter: element (j, i) of W^T
    ((unsigned short*)g_WHt)[(size_t)j * Hn + i] = __bfloat16_as_ushort(hi);
    ((unsigned short*)g_WLt)[(size_t)j * Hn + i] = __bfloat16_as_ushort(lo);
}

__global__ void init_state() {
    int idx = blockIdx.x * blockDim.x + threadIdx.x;
    if (idx < Bn * Hn / 2) { g_hpHu[0][idx] = 0u; g_hpLu[0][idx] = 0u; }
    if (idx == 0) { g_bar_count = 0; g_bar_gen = 0; }
}

// ---------------------------------------------------------------------------
// Drive precompute: drive[t,b,h] = 0.2*(stim·w_in + ctx·w_ctx + b_rec)
// ---------------------------------------------------------------------------
__global__ __launch_bounds__(256) void drive_kernel(
    const float* __restrict__ stim, const float* __restrict__ ctx,
    const float* __restrict__ w_in, const float* __restrict__ w_ctx,
    const float* __restrict__ b_rec)
{
    __shared__ __align__(16) float ws[72][68];
    __shared__ __align__(16) float xs[72][68];
    const int t  = blockIdx.x;
    const int h0 = blockIdx.y * 64;
    const int b0 = blockIdx.z * 64;
    const int tid = threadIdx.x;
    {
        int s = tid & 63, l0 = tid >> 6;
        for (int l = l0; l < 64; l += 4) {
            ws[s][l] = w_in[(h0 + l) * Sn + s];
            xs[s][l] = stim[((size_t)(b0 + l) * Tn + t) * Sn + s];
        }
        int c = tid & 7, m0 = tid >> 3;
        for (int l = m0; l < 64; l += 32) {
            ws[64 + c][l] = w_ctx[(h0 + l) * Cn + c];
            xs[64 + c][l] = ctx[((size_t)(b0 + l) * Tn + t) * Cn + c];
        }
    }
    __syncthreads();

    const int txh = tid & 15;
    const int tyb = tid >> 4;
    float acc[4][4] = {};
    #pragma unroll 8
    for (int k = 0; k < 72; k++) {
        float4 a = *(const float4*)&ws[k][txh * 4];
        float4 x = *(const float4*)&xs[k][tyb * 4];
        acc[0][0] += x.x * a.x; acc[0][1] += x.x * a.y; acc[0][2] += x.x * a.z; acc[0][3] += x.x * a.w;
        acc[1][0] += x.y * a.x; acc[1][1] += x.y * a.y; acc[1][2] += x.y * a.z; acc[1][3] += x.y * a.w;
        acc[2][0] += x.z * a.x; acc[2][1] += x.z * a.y; acc[2][2] += x.z * a.z; acc[2][3] += x.z * a.w;
        acc[3][0] += x.w * a.x; acc[3][1] += x.w * a.y; acc[3][2] += x.w * a.z; acc[3][3] += x.w * a.w;
    }

    float4 br = *(const float4*)&b_rec[h0 + txh * 4];
    const size_t base = (size_t)t * Bn * Hn;
    #pragma unroll
    for (int bb = 0; bb < 4; bb++) {
        int b = b0 + tyb * 4 + bb;
        float4 v = make_float4(0.2f * (acc[bb][0] + br.x),
                               0.2f * (acc[bb][1] + br.y),
                               0.2f * (acc[bb][2] + br.z),
                               0.2f * (acc[bb][3] + br.w));
        *(float4*)&g_drive[base + (size_t)b * Hn + h0 + txh * 4] = v;
    }
}

// ---------------------------------------------------------------------------
__device__ __forceinline__ void grid_bar(unsigned& genl) {
    __syncthreads();
    if (threadIdx.x == 0) {
        __threadfence();
        unsigned g = genl;
        unsigned old = atomicAdd(&g_bar_count, 1);
        if (old == NB - 1) {
            g_bar_count = 0;
            __threadfence();
            atomicAdd(&g_bar_gen, 1);
        } else {
            volatile unsigned* pg = &g_bar_gen;
            while (*pg <= g) { }
        }
        __threadfence();
        genl = g + 1;
    }
    __syncthreads();
}

#define MMA_BF16(acc, a, b)                                               \
    asm volatile(                                                         \
        "mma.sync.aligned.m16n8k16.row.col.f32.bf16.bf16.f32 "            \
        "{%0,%1,%2,%3}, {%4,%5,%6,%7}, {%8,%9}, {%0,%1,%2,%3};"           \
        : "+f"((acc)[0]), "+f"((acc)[1]), "+f"((acc)[2]), "+f"((acc)[3])  \
        : "r"((a)[0]), "r"((a)[1]), "r"((a)[2]), "r"((a)[3]),             \
          "r"((b)[0]), "r"((b)[1]))

// ---------------------------------------------------------------------------
// Persistent kernel. Per step:
//   stage hp hi/lo slice -> smem; bf16 split-precision tensor GEMM (3 mma
//   products into fp32 accum) -> g_part[ks]; grid_bar;
//   epilogue (split-K reduce + neuron + STP, state in regs, emit bf16 hp);
//   grid_bar.
// ---------------------------------------------------------------------------
__global__ __launch_bounds__(NT, 1) void rnn_persistent(
    const float* __restrict__ noise, float* __restrict__ acts)
{
    extern __shared__ unsigned smu[];
    unsigned* WHw = smu;                       // [TJ][ROWW]
    unsigned* WLw = WHw + TJ * ROWW;
    unsigned* HHw = WLw + TJ * ROWW;           // [TB][ROWW]
    unsigned* HLw = HHw + TB * ROWW;

    const int tid  = threadIdx.x;
    const int bid  = blockIdx.x;
    const int tile = bid >> 3;
    const int ks   = bid & 7;
    const int j0 = (tile >> 1) * TJ;
    const int b0 = (tile & 1) * TB;
    const int kw0 = ks * (KS / 2);             // word offset of k-slice in packed rows

    // ---- load W slices once (resident across all steps) ----
    for (int i = tid; i < TJ * (KS / 2); i += NT) {
        int r = i >> 6, c = i & 63;
        size_t ga = (size_t)(j0 + r) * (Hn / 2) + kw0 + c;
        WHw[r * ROWW + c] = g_WHt[ga];
        WLw[r * ROWW + c] = g_WLt[ga];
    }

    // ---- epilogue ownership: 4 consecutive j at fixed b, state in regs ----
    const int gtid = bid * NT + tid;
    const int e0 = gtid * 4;
    const int eb = e0 >> 10;
    const int ej = e0 & 1023;
    float hr[4]  = {0.f, 0.f, 0.f, 0.f};
    float sxr[4] = {1.f, 1.f, 1.f, 1.f};
    float sur[4] = {0.45f, 0.15f, 0.45f, 0.15f};
    const float axc[4] = {20.f/1500.f, 0.1f, 20.f/1500.f, 0.1f};
    const float Uc[4]  = {0.45f, 0.15f, 0.45f, 0.15f};

    // ---- mma lane mapping ----
    const int lane  = tid & 31;
    const int warp  = tid >> 5;
    const int wb    = warp & 1;          // b 32-tile within block
    const int wj    = warp >> 1;         // j 32-tile within block
    const int group = lane >> 2;
    const int tig   = lane & 3;

    unsigned genl = 0;
    __syncthreads();

    for (int t = 0; t < Tn; t++) {
        const int p = t & 1;

        // ---- stage hp hi/lo slice [b0..b0+63][k-slice] ----
        for (int i = tid; i < TB * (KS / 2); i += NT) {
            int r = i >> 6, c = i & 63;
            size_t ga = (size_t)(b0 + r) * (Hn / 2) + kw0 + c;
            HHw[r * ROWW + c] = g_hpHu[p][ga];
            HLw[r * ROWW + c] = g_hpLu[p][ga];
        }
        __syncthreads();

        // ---- tensor GEMM: warp tile 32b x 32j, K=128, 3-product bf16 split ----
        float acc[2][4][4];
        #pragma unroll
        for (int mi = 0; mi < 2; mi++)
            #pragma unroll
            for (int ni = 0; ni < 4; ni++)
                #pragma unroll
                for (int c = 0; c < 4; c++) acc[mi][ni][c] = 0.f;

        #pragma unroll 2
        for (int kt = 0; kt < KS / 16; kt++) {
            const int kw = kt * 8 + tig;
            unsigned ah[2][4], al[2][4];
            #pragma unroll
            for (int mi = 0; mi < 2; mi++) {
                int r0 = (wb * 32 + mi * 16 + group) * ROWW;
                int r1 = r0 + 8 * ROWW;
                ah[mi][0] = HHw[r0 + kw];     ah[mi][1] = HHw[r1 + kw];
                ah[mi][2] = HHw[r0 + kw + 4]; ah[mi][3] = HHw[r1 + kw + 4];
                al[mi][0] = HLw[r0 + kw];     al[mi][1] = HLw[r1 + kw];
                al[mi][2] = HLw[r0 + kw + 4]; al[mi][3] = HLw[r1 + kw + 4];
            }
            unsigned bh[4][2], bl[4][2];
            #pragma unroll
            for (int ni = 0; ni < 4; ni++) {
                int jr = (wj * 32 + ni * 8 + group) * ROWW;
                bh[ni][0] = WHw[jr + kw]; bh[ni][1] = WHw[jr + kw + 4];
                bl[ni][0] = WLw[jr + kw]; bl[ni][1] = WLw[jr + kw + 4];
            }
            #pragma unroll
            for (int mi = 0; mi < 2; mi++)
                #pragma unroll
                for (int ni = 0; ni < 4; ni++) {
                    MMA_BF16(acc[mi][ni], ah[mi], bh[ni]);
                    MMA_BF16(acc[mi][ni], ah[mi], bl[ni]);
                    MMA_BF16(acc[mi][ni], al[mi], bh[ni]);
                }
        }

        // ---- store partials: D[row=b][col=j] fragments ----
        {
            float* gp = g_part[ks];
            const int rb = b0 + wb * 32 + group;
            const int jc = j0 + wj * 32 + tig * 2;
            #pragma unroll
            for (int mi = 0; mi < 2; mi++)
                #pragma unroll
                for (int ni = 0; ni < 4; ni++) {
                    int r = rb + mi * 16;
                    int jj = jc + ni * 8;
                    *(float2*)&gp[(size_t)r * Hn + jj] =
                        make_float2(acc[mi][ni][0], acc[mi][ni][1]);
                    *(float2*)&gp[(size_t)(r + 8) * Hn + jj] =
                        make_float2(acc[mi][ni][2], acc[mi][ni][3]);
                }
        }

        grid_bar(genl);

        // ---- epilogue ----
        {
            const size_t pi = (size_t)eb * Hn + ej;
            float4 r = __ldcg((const float4*)&g_part[0][pi]);
            #pragma unroll
            for (int s = 1; s < KSPLIT; s++) {
                float4 q = __ldcg((const float4*)&g_part[s][pi]);
                r.x += q.x; r.y += q.y; r.z += q.z; r.w += q.w;
            }
            const size_t ti = ((size_t)t * Bn + eb) * Hn + ej;
            float4 d  = __ldcs((const float4*)&g_drive[ti]);
            float4 nz = __ldcs((const float4*)&noise[ti]);

            float rv[4] = {r.x, r.y, r.z, r.w};
            float dv[4] = {d.x, d.y, d.z, d.w};
            float nv[4] = {nz.x, nz.y, nz.z, nz.w};
            float hn[4];
            unsigned hpH[4], hpL[4];
            #pragma unroll
            for (int u = 0; u < 4; u++) {
                float h = fmaxf(0.8f * hr[u] + dv[u] + 0.2f * rv[u] + 0.05f * nv[u], 0.f);
                hn[u] = h;
                float sx = sxr[u], su = sur[u];
                float ax = axc[u], U = Uc[u];
                float sxn = sx + ax * (1.f - sx) - 0.02f * su * sx * h;
                sxn = fminf(fmaxf(sxn, 0.f), 1.f);
                float sun = su + ax * (U - su) + 0.02f * U * (1.f - su) * h;
                sun = fminf(fmaxf(sun, 0.f), 1.f);
                hr[u] = h; sxr[u] = sxn; sur[u] = sun;
                float hp = sun * sxn * h;
                __nv_bfloat16 hi = __float2bfloat16_rn(hp);
                __nv_bfloat16 lo = __float2bfloat16_rn(hp - __bfloat162float(hi));
                hpH[u] = (unsigned)__bfloat16_as_ushort(hi);
                hpL[u] = (unsigned)__bfloat16_as_ushort(lo);
            }
            const size_t hw = ((size_t)eb * Hn + ej) >> 1;   // packed word index
            g_hpHu[p ^ 1][hw]     = hpH[0] | (hpH[1] << 16);
            g_hpHu[p ^ 1][hw + 1] = hpH[2] | (hpH[3] << 16);
            g_hpLu[p ^ 1][hw]     = hpL[0] | (hpL[1] << 16);
            g_hpLu[p ^ 1][hw + 1] = hpL[2] | (hpL[3] << 16);

            *(float4*)&acts[((size_t)eb * Tn + t) * Hn + ej] =
                make_float4(hn[0], hn[1], hn[2], hn[3]);
        }

        grid_bar(genl);
    }
}

// ---------------------------------------------------------------------------
__global__ __launch_bounds__(128) void head_kernel(
    const float* __restrict__ acts, const float* __restrict__ w_out,
    const float* __restrict__ b_out, const float* __restrict__ c1_w,
    const float* __restrict__ c1_b, const float* __restrict__ c2_w,
    const float* __restrict__ c2_b, float* __restrict__ outputs,
    float* __restrict__ p)
{
    const int t = blockIdx.x, b = blockIdx.y;
    const int tid = threadIdx.x;
    float s[9] = {};
    const float* arow = acts + ((size_t)b * Tn + t) * Hn;
    for (int h = tid; h < Hn; h += 128) {
        float a = arow[h];
        #pragma unroll
        for (int o = 0; o < 3; o++) s[o] = fmaf(a, w_out[o * Hn + h], s[o]);
        #pragma unroll
        for (int m = 0; m < 6; m++) s[3 + m] = fmaf(a, c1_w[m * Hn + h], s[3 + m]);
    }
    __shared__ float red[9][128];
    #pragma unroll
    for (int q = 0; q < 9; q++) red[q][tid] = s[q];
    __syncthreads();
    for (int st = 64; st > 0; st >>= 1) {
        if (tid < st) {
            #pragma unroll
            for (int q = 0; q < 9; q++) red[q][tid] += red[q][tid + st];
        }
        __syncthreads();
    }
    if (tid == 0) {
        size_t ob = ((size_t)b * Tn + t) * 3;
        #pragma unroll
        for (int o = 0; o < 3; o++) outputs[ob + o] = red[o][0] + b_out[o];
        float z[6];
        #pragma unroll
        for (int m = 0; m < 6; m++) z[m] = red[3 + m][0] + c1_b[m];
        size_t pb = ((size_t)b * Tn + t) * 24;
        #pragma unroll
        for (int j = 0; j < 3; j++)
            #pragma unroll
            for (int o = 0; o < 8; o++)
                p[pb + j * 8 + o] = c2_b[j * 8 + o]
                                  + z[j * 2 + 0] * c2_w[j * 16 + o * 2 + 0]
                                  + z[j * 2 + 1] * c2_w[j * 16 + o * 2 + 1];
    }
}

// ---------------------------------------------------------------------------
extern "C" void kernel_launch(void* const* d_in, const int* in_sizes, int n_in,
                              void* d_out, int out_size)
{
    (void)in_sizes; (void)n_in; (void)out_size;
    const float* stim  = (const float*)d_in[0];
    const float* ctx   = (const float*)d_in[1];
    const float* w_rec = (const float*)d_in[2];
    const float* b_rec = (const float*)d_in[3];
    const float* w_in  = (const float*)d_in[4];
    const float* w_ctx = (const float*)d_in[5];
    const float* w_out = (const float*)d_in[6];
    const float* b_out = (const float*)d_in[7];
    const float* c1_w  = (const float*)d_in[8];
    const float* c1_b  = (const float*)d_in[9];
    const float* c2_w  = (const float*)d_in[10];
    const float* c2_b  = (const float*)d_in[11];
    const float* noise = (const float*)d_in[12];

    float* out      = (float*)d_out;
    float* outputs  = out;                              // [B,T,3]
    float* acts     = out + (size_t)Bn * Tn * 3;        // [B,T,H]
    float* p        = acts + (size_t)Bn * Tn * Hn;      // [B,T,3,8]

    const int smem_bytes = (2 * TJ * ROWW + 2 * TB * ROWW) * (int)sizeof(unsigned);
    static bool attr_set = false;
    if (!attr_set) {
        cudaFuncSetAttribute(rnn_persistent,
                             cudaFuncAttributeMaxDynamicSharedMemorySize,
                             smem_bytes);
        attr_set = true;
    }

    prep_W<<<(Hn * Hn) / 256, 256>>>(w_rec);
    init_state<<<(Bn * Hn) / 256, 256>>>();
    drive_kernel<<<dim3(Tn, Hn / 64, Bn / 64), 256>>>(stim, ctx, w_in, w_ctx, b_rec);

    rnn_persistent<<<NB, NT, smem_bytes>>>(noise, acts);

    head_kernel<<<dim3(Tn, Bn), 128>>>(acts, w_out, b_out, c1_w, c1_b,
                                       c2_w, c2_b, outputs, p);
}

// round 14
// speedup vs baseline: 2.5354x; 1.0951x over previous
#include <cuda_runtime.h>
#include <cuda_bf16.h>
#include <cstddef>

#define Hn 1024
#define Bn 128
#define Tn 400
#define Sn 64
#define Cn 8
#define NEXC 819

// persistent-kernel config
#define NB 128      // blocks (all co-resident: 1/SM)
#define NT 256      // threads per block
#define KSPLIT 8
#define KS 128      // Hn / KSPLIT
#define TJ 128      // j-tile
#define TB 64       // b-tile
#define ROWW 68     // padded smem row width in words (64 data + 4 pad, 16B-aligned rows)
#define NGRP 16     // tile groups (8 j-tiles x 2 b-tiles)

// ---- scratch (__device__ globals) ----
__device__ unsigned g_WHt[Hn * Hn / 2];          // bf16 hi of W^T: [j][i], packed pairs
__device__ unsigned g_WLt[Hn * Hn / 2];          // bf16 lo of W^T
__device__ float    g_drive[(size_t)Tn * Bn * Hn];
__device__ unsigned g_hpHu[2][Bn * Hn / 2];      // h_post bf16 hi, [parity][b][i] packed
__device__ unsigned g_hpLu[2][Bn * Hn / 2];      // h_post bf16 lo
__device__ float    g_part[KSPLIT][Bn * Hn];     // split-K partials [ks][b][j]
__device__ unsigned g_grp_cnt[NGRP];             // arrival counters (monotonic)
__device__ unsigned g_grp_done[NGRP];            // completed-phase count (monotonic)

// ---------------------------------------------------------------------------
__global__ void prep_W(const float* __restrict__ w_rec) {
    int o = blockIdx.x * blockDim.x + threadIdx.x;   // o = i*H + j
    int i = o >> 10;
    int j = o & 1023;
    float v = fmaxf(w_rec[o], 0.f);
    if (i == j) v = 0.f;
    v = (i < NEXC) ? v : -v;
    __nv_bfloat16 hi = __float2bfloat16_rn(v);
    float hif = __bfloat162float(hi);
    __nv_bfloat16 lo = __float2bfloat16_rn(v - hif);
    ((unsigned short*)g_WHt)[(size_t)j * Hn + i] = __bfloat16_as_ushort(hi);
    ((unsigned short*)g_WLt)[(size_t)j * Hn + i] = __bfloat16_as_ushort(lo);
}

__global__ void init_state() {
    int idx = blockIdx.x * blockDim.x + threadIdx.x;
    if (idx < Bn * Hn / 2) { g_hpHu[0][idx] = 0u; g_hpLu[0][idx] = 0u; }
    if (idx < NGRP) { g_grp_cnt[idx] = 0; g_grp_done[idx] = 0; }
}

// ---------------------------------------------------------------------------
// Drive precompute: drive[t,b,h] = 0.2*(stim·w_in + ctx·w_ctx + b_rec)
// ---------------------------------------------------------------------------
__global__ __launch_bounds__(256) void drive_kernel(
    const float* __restrict__ stim, const float* __restrict__ ctx,
    const float* __restrict__ w_in, const float* __restrict__ w_ctx,
    const float* __restrict__ b_rec)
{
    __shared__ __align__(16) float ws[72][68];
    __shared__ __align__(16) float xs[72][68];
    const int t  = blockIdx.x;
    const int h0 = blockIdx.y * 64;
    const int b0 = blockIdx.z * 64;
    const int tid = threadIdx.x;
    {
        int s = tid & 63, l0 = tid >> 6;
        for (int l = l0; l < 64; l += 4) {
            ws[s][l] = w_in[(h0 + l) * Sn + s];
            xs[s][l] = stim[((size_t)(b0 + l) * Tn + t) * Sn + s];
        }
        int c = tid & 7, m0 = tid >> 3;
        for (int l = m0; l < 64; l += 32) {
            ws[64 + c][l] = w_ctx[(h0 + l) * Cn + c];
            xs[64 + c][l] = ctx[((size_t)(b0 + l) * Tn + t) * Cn + c];
        }
    }
    __syncthreads();

    const int txh = tid & 15;
    const int tyb = tid >> 4;
    float acc[4][4] = {};
    #pragma unroll 8
    for (int k = 0; k < 72; k++) {
        float4 a = *(const float4*)&ws[k][txh * 4];
        float4 x = *(const float4*)&xs[k][tyb * 4];
        acc[0][0] += x.x * a.x; acc[0][1] += x.x * a.y; acc[0][2] += x.x * a.z; acc[0][3] += x.x * a.w;
        acc[1][0] += x.y * a.x; acc[1][1] += x.y * a.y; acc[1][2] += x.y * a.z; acc[1][3] += x.y * a.w;
        acc[2][0] += x.z * a.x; acc[2][1] += x.z * a.y; acc[2][2] += x.z * a.z; acc[2][3] += x.z * a.w;
        acc[3][0] += x.w * a.x; acc[3][1] += x.w * a.y; acc[3][2] += x.w * a.z; acc[3][3] += x.w * a.w;
    }

    float4 br = *(const float4*)&b_rec[h0 + txh * 4];
    const size_t base = (size_t)t * Bn * Hn;
    #pragma unroll
    for (int bb = 0; bb < 4; bb++) {
        int b = b0 + tyb * 4 + bb;
        float4 v = make_float4(0.2f * (acc[bb][0] + br.x),
                               0.2f * (acc[bb][1] + br.y),
                               0.2f * (acc[bb][2] + br.z),
                               0.2f * (acc[bb][3] + br.w));
        *(float4*)&g_drive[base + (size_t)b * Hn + h0 + txh * 4] = v;
    }
}

// ---------------------------------------------------------------------------
// Group sync primitives (thread0 only; caller wraps with __syncthreads)
// ---------------------------------------------------------------------------
__device__ __forceinline__ void grp_arrive(int grp) {
    unsigned old = atomicAdd(&g_grp_cnt[grp], 1);
    if ((old & 7) == 7) {                       // 8th arrival of this phase
        __threadfence();
        atomicExch(&g_grp_done[grp], (old + 1) >> 3);
    }
}
__device__ __forceinline__ void grp_wait(int grp, unsigned target) {
    volatile unsigned* pd = &g_grp_done[grp];
    while (*pd < target) { }
}

#define MMA_BF16(acc, a, b)                                               \
    asm volatile(                                                         \
        "mma.sync.aligned.m16n8k16.row.col.f32.bf16.bf16.f32 "            \
        "{%0,%1,%2,%3}, {%4,%5,%6,%7}, {%8,%9}, {%0,%1,%2,%3};"           \
        : "+f"((acc)[0]), "+f"((acc)[1]), "+f"((acc)[2]), "+f"((acc)[3])  \
        : "r"((a)[0]), "r"((a)[1]), "r"((a)[2]), "r"((a)[3]),             \
          "r"((b)[0]), "r"((b)[1]))

// ---------------------------------------------------------------------------
// Persistent kernel. Per step, block (jt,bt,ks):
//   prefetch drive/noise (regs) ;
//   wait done[(ks,bt)]>=2t && done[(jt,bt)]>=2t ;
//   stage hp slice ; mma (3-product bf16 split) ; store partials ;
//   arrive own grp (phase 2t+1) ; wait own grp >= 2t+1 ;
//   epilogue over OWN tile's 1024 elements (reads 8 sibling partials from L2,
//   STP state in regs, writes hp hi/lo + acts) ;
//   arrive own grp (phase 2t+2).
// No grid-wide barrier anywhere: groups pipeline around each other.
// ---------------------------------------------------------------------------
__global__ __launch_bounds__(NT, 1) void rnn_persistent(
    const float* __restrict__ noise, float* __restrict__ acts)
{
    extern __shared__ unsigned smu[];
    unsigned* WHw = smu;                       // [TJ][ROWW]
    unsigned* WLw = WHw + TJ * ROWW;
    unsigned* HHw = WLw + TJ * ROWW;           // [TB][ROWW]
    unsigned* HLw = HHw + TB * ROWW;

    const int tid  = threadIdx.x;
    const int bid  = blockIdx.x;
    const int tile = bid >> 3;                 // = jt*2 + btile
    const int ks   = bid & 7;
    const int j0 = (tile >> 1) * TJ;
    const int b0 = (tile & 1) * TB;
    const int kw0 = ks * (KS / 2);             // word offset of k-slice

    const int grp_own = tile;
    const int grp_hp  = ks * 2 + (tile & 1);   // producers of the hp slice we stage

    // ---- load W slices once (resident across all steps) ----
    for (int i = tid; i < TJ * (KS / 8); i += NT) {       // 128 rows x 16 float4
        int r = i >> 4, c4 = i & 15;
        size_t ga = (size_t)(j0 + r) * (Hn / 2) + kw0 + c4 * 4;
        *(uint4*)&WHw[r * ROWW + c4 * 4] = *(const uint4*)&g_WHt[ga];
        *(uint4*)&WLw[r * ROWW + c4 * 4] = *(const uint4*)&g_WLt[ga];
    }

    // ---- epilogue ownership: 4 consecutive j within OWN tile ----
    const int eb = b0 + ks * 8 + (tid >> 5);
    const int ej = j0 + 4 * (tid & 31);
    float hr[4]  = {0.f, 0.f, 0.f, 0.f};
    float sxr[4] = {1.f, 1.f, 1.f, 1.f};
    float sur[4] = {0.45f, 0.15f, 0.45f, 0.15f};
    const float axc[4] = {20.f/1500.f, 0.1f, 20.f/1500.f, 0.1f};
    const float Uc[4]  = {0.45f, 0.15f, 0.45f, 0.15f};

    // ---- mma lane mapping ----
    const int lane  = tid & 31;
    const int warp  = tid >> 5;
    const int wb    = warp & 1;          // b 32-tile within block
    const int wj    = warp >> 1;         // j 32-tile within block
    const int group = lane >> 2;
    const int tig   = lane & 3;

    __syncthreads();

    for (int t = 0; t < Tn; t++) {
        const int p = t & 1;

        // ---- prefetch drive/noise for this step's epilogue elements ----
        const size_t ti = ((size_t)t * Bn + eb) * Hn + ej;
        float4 d4  = __ldcs((const float4*)&g_drive[ti]);
        float4 nz4 = __ldcs((const float4*)&noise[ti]);

        // ---- wait: hp inputs ready + own partial slot free ----
        if (tid == 0) {
            if (t > 0) {
                grp_wait(grp_hp,  2u * t);
                grp_wait(grp_own, 2u * t);
            }
        }
        __syncthreads();

        // ---- stage hp hi/lo slice [b0..b0+63][k-slice] (float4) ----
        for (int i = tid; i < TB * (KS / 8); i += NT) {   // 64 rows x 16 float4
            int r = i >> 4, c4 = i & 15;
            size_t ga = (size_t)(b0 + r) * (Hn / 2) + kw0 + c4 * 4;
            uint4 vh, vl;
            vh.x = __ldcg(&g_hpHu[p][ga]);     vl.x = __ldcg(&g_hpLu[p][ga]);
            vh.y = __ldcg(&g_hpHu[p][ga + 1]); vl.y = __ldcg(&g_hpLu[p][ga + 1]);
            vh.z = __ldcg(&g_hpHu[p][ga + 2]); vl.z = __ldcg(&g_hpLu[p][ga + 2]);
            vh.w = __ldcg(&g_hpHu[p][ga + 3]); vl.w = __ldcg(&g_hpLu[p][ga + 3]);
            *(uint4*)&HHw[r * ROWW + c4 * 4] = vh;
            *(uint4*)&HLw[r * ROWW + c4 * 4] = vl;
        }
        __syncthreads();

        // ---- tensor GEMM: warp tile 32b x 32j, K=128, 3-product bf16 split ----
        float acc[2][4][4];
        #pragma unroll
        for (int mi = 0; mi < 2; mi++)
            #pragma unroll
            for (int ni = 0; ni < 4; ni++)
                #pragma unroll
                for (int c = 0; c < 4; c++) acc[mi][ni][c] = 0.f;

        #pragma unroll 2
        for (int kt = 0; kt < KS / 16; kt++) {
            const int kw = kt * 8 + tig;
            unsigned ah[2][4], al[2][4];
            #pragma unroll
            for (int mi = 0; mi < 2; mi++) {
                int r0 = (wb * 32 + mi * 16 + group) * ROWW;
                int r1 = r0 + 8 * ROWW;
                ah[mi][0] = HHw[r0 + kw];     ah[mi][1] = HHw[r1 + kw];
                ah[mi][2] = HHw[r0 + kw + 4]; ah[mi][3] = HHw[r1 + kw + 4];
                al[mi][0] = HLw[r0 + kw];     al[mi][1] = HLw[r1 + kw];
                al[mi][2] = HLw[r0 + kw + 4]; al[mi][3] = HLw[r1 + kw + 4];
            }
            unsigned bh[4][2], bl[4][2];
            #pragma unroll
            for (int ni = 0; ni < 4; ni++) {
                int jr = (wj * 32 + ni * 8 + group) * ROWW;
                bh[ni][0] = WHw[jr + kw]; bh[ni][1] = WHw[jr + kw + 4];
                bl[ni][0] = WLw[jr + kw]; bl[ni][1] = WLw[jr + kw + 4];
            }
            #pragma unroll
            for (int mi = 0; mi < 2; mi++)
                #pragma unroll
                for (int ni = 0; ni < 4; ni++) {
                    MMA_BF16(acc[mi][ni], ah[mi], bh[ni]);
                    MMA_BF16(acc[mi][ni], ah[mi], bl[ni]);
                    MMA_BF16(acc[mi][ni], al[mi], bh[ni]);
                }
        }

        // ---- store partials ----
        {
            float* gp = g_part[ks];
            const int rb = b0 + wb * 32 + group;
            const int jc = j0 + wj * 32 + tig * 2;
            #pragma unroll
            for (int mi = 0; mi < 2; mi++)
                #pragma unroll
                for (int ni = 0; ni < 4; ni++) {
                    int r = rb + mi * 16;
                    int jj = jc + ni * 8;
                    *(float2*)&gp[(size_t)r * Hn + jj] =
                        make_float2(acc[mi][ni][0], acc[mi][ni][1]);
                    *(float2*)&gp[(size_t)(r + 8) * Hn + jj] =
                        make_float2(acc[mi][ni][2], acc[mi][ni][3]);
                }
        }

        __threadfence();
        __syncthreads();
        if (tid == 0) {
            grp_arrive(grp_own);                 // phase 2t+1
            grp_wait(grp_own, 2u * t + 1);
        }
        __syncthreads();

        // ---- epilogue over own tile's elements ----
        {
            const size_t pi = (size_t)eb * Hn + ej;
            float4 r = __ldcg((const float4*)&g_part[0][pi]);
            #pragma unroll
            for (int s = 1; s < KSPLIT; s++) {
                float4 q = __ldcg((const float4*)&g_part[s][pi]);
                r.x += q.x; r.y += q.y; r.z += q.z; r.w += q.w;
            }
            float rv[4] = {r.x, r.y, r.z, r.w};
            float dv[4] = {d4.x, d4.y, d4.z, d4.w};
            float nv[4] = {nz4.x, nz4.y, nz4.z, nz4.w};
            float hn[4];
            unsigned hpH[4], hpL[4];
            #pragma unroll
            for (int u = 0; u < 4; u++) {
                float h = fmaxf(0.8f * hr[u] + dv[u] + 0.2f * rv[u] + 0.05f * nv[u], 0.f);
                hn[u] = h;
                float sx = sxr[u], su = sur[u];
                float ax = axc[u], U = Uc[u];
                float sxn = sx + ax * (1.f - sx) - 0.02f * su * sx * h;
                sxn = fminf(fmaxf(sxn, 0.f), 1.f);
                float sun = su + ax * (U - su) + 0.02f * U * (1.f - su) * h;
                sun = fminf(fmaxf(sun, 0.f), 1.f);
                hr[u] = h; sxr[u] = sxn; sur[u] = sun;
                float hp = sun * sxn * h;
                __nv_bfloat16 hi = __float2bfloat16_rn(hp);
                __nv_bfloat16 lo = __float2bfloat16_rn(hp - __bfloat162float(hi));
                hpH[u] = (unsigned)__bfloat16_as_ushort(hi);
                hpL[u] = (unsigned)__bfloat16_as_ushort(lo);
            }
            const size_t hw = ((size_t)eb * Hn + ej) >> 1;
            g_hpHu[p ^ 1][hw]     = hpH[0] | (hpH[1] << 16);
            g_hpHu[p ^ 1][hw + 1] = hpH[2] | (hpH[3] << 16);
            g_hpLu[p ^ 1][hw]     = hpL[0] | (hpL[1] << 16);
            g_hpLu[p ^ 1][hw + 1] = hpL[2] | (hpL[3] << 16);

            *(float4*)&acts[((size_t)eb * Tn + t) * Hn + ej] =
                make_float4(hn[0], hn[1], hn[2], hn[3]);
        }

        __threadfence();
        __syncthreads();
        if (tid == 0) grp_arrive(grp_own);       // phase 2t+2
    }
}

// ---------------------------------------------------------------------------
__global__ __launch_bounds__(128) void head_kernel(
    const float* __restrict__ acts, const float* __restrict__ w_out,
    const float* __restrict__ b_out, const float* __restrict__ c1_w,
    const float* __restrict__ c1_b, const float* __restrict__ c2_w,
    const float* __restrict__ c2_b, float* __restrict__ outputs,
    float* __restrict__ p)
{
    const int t = blockIdx.x, b = blockIdx.y;
    const int tid = threadIdx.x;
    float s[9] = {};
    const float* arow = acts + ((size_t)b * Tn + t) * Hn;
    for (int h = tid; h < Hn; h += 128) {
        float a = arow[h];
        #pragma unroll
        for (int o = 0; o < 3; o++) s[o] = fmaf(a, w_out[o * Hn + h], s[o]);
        #pragma unroll
        for (int m = 0; m < 6; m++) s[3 + m] = fmaf(a, c1_w[m * Hn + h], s[3 + m]);
    }
    __shared__ float red[9][128];
    #pragma unroll
    for (int q = 0; q < 9; q++) red[q][tid] = s[q];
    __syncthreads();
    for (int st = 64; st > 0; st >>= 1) {
        if (tid < st) {
            #pragma unroll
            for (int q = 0; q < 9; q++) red[q][tid] += red[q][tid + st];
        }
        __syncthreads();
    }
    if (tid == 0) {
        size_t ob = ((size_t)b * Tn + t) * 3;
        #pragma unroll
        for (int o = 0; o < 3; o++) outputs[ob + o] = red[o][0] + b_out[o];
        float z[6];
        #pragma unroll
        for (int m = 0; m < 6; m++) z[m] = red[3 + m][0] + c1_b[m];
        size_t pb = ((size_t)b * Tn + t) * 24;
        #pragma unroll
        for (int j = 0; j < 3; j++)
            #pragma unroll
            for (int o = 0; o < 8; o++)
                p[pb + j * 8 + o] = c2_b[j * 8 + o]
                                  + z[j * 2 + 0] * c2_w[j * 16 + o * 2 + 0]
                                  + z[j * 2 + 1] * c2_w[j * 16 + o * 2 + 1];
    }
}

// ---------------------------------------------------------------------------
extern "C" void kernel_launch(void* const* d_in, const int* in_sizes, int n_in,
                              void* d_out, int out_size)
{
    (void)in_sizes; (void)n_in; (void)out_size;
    const float* stim  = (const float*)d_in[0];
    const float* ctx   = (const float*)d_in[1];
    const float* w_rec = (const float*)d_in[2];
    const float* b_rec = (const float*)d_in[3];
    const float* w_in  = (const float*)d_in[4];
    const float* w_ctx = (const float*)d_in[5];
    const float* w_out = (const float*)d_in[6];
    const float* b_out = (const float*)d_in[7];
    const float* c1_w  = (const float*)d_in[8];
    const float* c1_b  = (const float*)d_in[9];
    const float* c2_w  = (const float*)d_in[10];
    const float* c2_b  = (const float*)d_in[11];
    const float* noise = (const float*)d_in[12];

    float* out      = (float*)d_out;
    float* outputs  = out;                              // [B,T,3]
    float* acts     = out + (size_t)Bn * Tn * 3;        // [B,T,H]
    float* p        = acts + (size_t)Bn * Tn * Hn;      // [B,T,3,8]

    const int smem_bytes = (2 * TJ * ROWW + 2 * TB * ROWW) * (int)sizeof(unsigned);
    static bool attr_set = false;
    if (!attr_set) {
        cudaFuncSetAttribute(rnn_persistent,
                             cudaFuncAttributeMaxDynamicSharedMemorySize,
                             smem_bytes);
        attr_set = true;
    }

    prep_W<<<(Hn * Hn) / 256, 256>>>(w_rec);
    init_state<<<(Bn * Hn) / 256, 256>>>();
    drive_kernel<<<dim3(Tn, Hn / 64, Bn / 64), 256>>>(stim, ctx, w_in, w_ctx, b_rec);

    rnn_persistent<<<NB, NT, smem_bytes>>>(noise, acts);

    head_kernel<<<dim3(Tn, Bn), 128>>>(acts, w_out, b_out, c1_w, c1_b,
                                       c2_w, c2_b, outputs, p);
}

// round 17
// speedup vs baseline: 3.4495x; 1.3605x over previous
#include <cuda_runtime.h>
#include <cuda_bf16.h>
#include <cstddef>

#define Hn 1024
#define Bn 128
#define Tn 400
#define Sn 64
#define Cn 8
#define NEXC 819

// persistent-kernel config
#define NB 128      // blocks (all co-resident: 1/SM)
#define NT 256      // threads per block
#define KSPLIT 8
#define KS 128      // Hn / KSPLIT
#define TJ 128      // j-tile
#define TB 64       // b-tile
#define ROWW 68     // padded smem row width in words (64 data + 4 pad, 16B-aligned rows)
#define NGRP 16     // tile groups (8 j-tiles x 2 b-tiles)

// ---- scratch (__device__ globals) ----
__device__ unsigned g_WHt[Hn * Hn / 2];          // bf16 hi of 0.2*W^T: [j][i], packed pairs
__device__ unsigned g_WLt[Hn * Hn / 2];          // bf16 lo
__device__ float    g_dn[(size_t)Tn * Bn * Hn];  // 0.2*(ff+b_rec)+0.05*noise, [t][b][h]
__device__ unsigned g_hpHu[2][Bn * Hn / 2];      // h_post bf16 hi, [parity][b][i] packed
__device__ unsigned g_hpLu[2][Bn * Hn / 2];      // h_post bf16 lo
__device__ float    g_part[2][KSPLIT][Bn * Hn];  // split-K partials [parity][ks][b][j]
__device__ unsigned g_cnt_part[NGRP];            // monotonic arrival counters
__device__ unsigned g_cnt_epi[NGRP];

// ---------------------------------------------------------------------------
__global__ void prep_W(const float* __restrict__ w_rec) {
    int o = blockIdx.x * blockDim.x + threadIdx.x;   // o = i*H + j
    int i = o >> 10;
    int j = o & 1023;
    float v = fmaxf(w_rec[o], 0.f);
    if (i == j) v = 0.f;
    v = (i < NEXC) ? v : -v;
    v *= 0.2f;                                        // fold ALPHA_N into W
    __nv_bfloat16 hi = __float2bfloat16_rn(v);
    float hif = __bfloat162float(hi);
    __nv_bfloat16 lo = __float2bfloat16_rn(v - hif);
    ((unsigned short*)g_WHt)[(size_t)j * Hn + i] = __bfloat16_as_ushort(hi);
    ((unsigned short*)g_WLt)[(size_t)j * Hn + i] = __bfloat16_as_ushort(lo);
}

__global__ void init_state() {
    int idx = blockIdx.x * blockDim.x + threadIdx.x;
    if (idx < Bn * Hn / 2) { g_hpHu[0][idx] = 0u; g_hpLu[0][idx] = 0u; }
    if (idx < NGRP) { g_cnt_part[idx] = 0; g_cnt_epi[idx] = 0; }
}

// ---------------------------------------------------------------------------
// Drive precompute: dn[t,b,h] = 0.2*(stim·w_in + ctx·w_ctx + b_rec) + 0.05*noise
// ---------------------------------------------------------------------------
__global__ __launch_bounds__(256) void drive_kernel(
    const float* __restrict__ stim, const float* __restrict__ ctx,
    const float* __restrict__ w_in, const float* __restrict__ w_ctx,
    const float* __restrict__ b_rec, const float* __restrict__ noise)
{
    __shared__ __align__(16) float ws[72][68];
    __shared__ __align__(16) float xs[72][68];
    const int t  = blockIdx.x;
    const int h0 = blockIdx.y * 64;
    const int b0 = blockIdx.z * 64;
    const int tid = threadIdx.x;
    {
        int s = tid & 63, l0 = tid >> 6;
        for (int l = l0; l < 64; l += 4) {
            ws[s][l] = w_in[(h0 + l) * Sn + s];
            xs[s][l] = stim[((size_t)(b0 + l) * Tn + t) * Sn + s];
        }
        int c = tid & 7, m0 = tid >> 3;
        for (int l = m0; l < 64; l += 32) {
            ws[64 + c][l] = w_ctx[(h0 + l) * Cn + c];
            xs[64 + c][l] = ctx[((size_t)(b0 + l) * Tn + t) * Cn + c];
        }
    }
    __syncthreads();

    const int txh = tid & 15;
    const int tyb = tid >> 4;
    float acc[4][4] = {};
    #pragma unroll 8
    for (int k = 0; k < 72; k++) {
        float4 a = *(const float4*)&ws[k][txh * 4];
        float4 x = *(const float4*)&xs[k][tyb * 4];
        acc[0][0] += x.x * a.x; acc[0][1] += x.x * a.y; acc[0][2] += x.x * a.z; acc[0][3] += x.x * a.w;
        acc[1][0] += x.y * a.x; acc[1][1] += x.y * a.y; acc[1][2] += x.y * a.z; acc[1][3] += x.y * a.w;
        acc[2][0] += x.z * a.x; acc[2][1] += x.z * a.y; acc[2][2] += x.z * a.z; acc[2][3] += x.z * a.w;
        acc[3][0] += x.w * a.x; acc[3][1] += x.w * a.y; acc[3][2] += x.w * a.z; acc[3][3] += x.w * a.w;
    }

    float4 br = *(const float4*)&b_rec[h0 + txh * 4];
    const size_t base = (size_t)t * Bn * Hn;
    #pragma unroll
    for (int bb = 0; bb < 4; bb++) {
        int b = b0 + tyb * 4 + bb;
        size_t ix = base + (size_t)b * Hn + h0 + txh * 4;
        float4 nz = *(const float4*)&noise[ix];
        float4 v = make_float4(0.2f * (acc[bb][0] + br.x) + 0.05f * nz.x,
                               0.2f * (acc[bb][1] + br.y) + 0.05f * nz.y,
                               0.2f * (acc[bb][2] + br.z) + 0.05f * nz.z,
                               0.2f * (acc[bb][3] + br.w) + 0.05f * nz.w);
        *(float4*)&g_dn[ix] = v;
    }
}

// ---------------------------------------------------------------------------
// CG-style sync primitives: bar.sync -> elected red.release; ld.acquire spin.
// No threadfence anywhere (no L1 invalidates, no RMW return latency).
// ---------------------------------------------------------------------------
__device__ __forceinline__ void red_rel(unsigned* p) {
    asm volatile("red.release.gpu.global.add.u32 [%0], 1;" :: "l"(p) : "memory");
}
__device__ __forceinline__ unsigned ld_acq(const unsigned* p) {
    unsigned v;
    asm volatile("ld.acquire.gpu.global.u32 %0, [%1];" : "=r"(v) : "l"(p) : "memory");
    return v;
}
__device__ __forceinline__ void cpa16(unsigned smem_addr, const void* g) {
    asm volatile("cp.async.cg.shared.global [%0], [%1], 16;"
                 :: "r"(smem_addr), "l"(g) : "memory");
}

#define MMA_BF16(acc, a, b)                                               \
    asm volatile(                                                         \
        "mma.sync.aligned.m16n8k16.row.col.f32.bf16.bf16.f32 "            \
        "{%0,%1,%2,%3}, {%4,%5,%6,%7}, {%8,%9}, {%0,%1,%2,%3};"           \
        : "+f"((acc)[0]), "+f"((acc)[1]), "+f"((acc)[2]), "+f"((acc)[3])  \
        : "r"((a)[0]), "r"((a)[1]), "r"((a)[2]), "r"((a)[3]),             \
          "r"((b)[0]), "r"((b)[1]))

// ---------------------------------------------------------------------------
// Persistent kernel. Per step, block (jt,bt,ks):
//   prefetch dn (regs) ;
//   wait cnt_epi[grp_hp] >= 8t ; cp.async-stage hp[p] ; mma ;
//   wait cnt_epi[grp_own] >= 8(t-1)   (WAR on g_part[p], 2-step-old: free) ;
//   store partials[p] ; arrive cnt_part[own] ; wait cnt_part[own] >= 8(t+1) ;
//   epilogue (1024 own elems: split-K reduce, STP in regs, hp[p^1] + acts) ;
//   arrive cnt_epi[own].
// ---------------------------------------------------------------------------
__global__ __launch_bounds__(NT, 1) void rnn_persistent(float* __restrict__ acts)
{
    extern __shared__ unsigned smu[];
    unsigned* WHw = smu;                       // [TJ][ROWW]
    unsigned* WLw = WHw + TJ * ROWW;
    unsigned* HHw = WLw + TJ * ROWW;           // [TB][ROWW]
    unsigned* HLw = HHw + TB * ROWW;
    const unsigned sHH = (unsigned)__cvta_generic_to_shared(HHw);
    const unsigned sHL = (unsigned)__cvta_generic_to_shared(HLw);

    const int tid  = threadIdx.x;
    const int bid  = blockIdx.x;
    const int tile = bid >> 3;                 // = jt*2 + btile
    const int ks   = bid & 7;
    const int j0 = (tile >> 1) * TJ;
    const int b0 = (tile & 1) * TB;
    const int kw0 = ks * (KS / 2);             // word offset of k-slice

    const int grp_own = tile;
    const int grp_hp  = ks * 2 + (tile & 1);   // producers of the hp slice we stage

    // ---- load W slices once (resident across all steps) ----
    for (int i = tid; i < TJ * (KS / 8); i += NT) {       // 128 rows x 16 float4
        int r = i >> 4, c4 = i & 15;
        size_t ga = (size_t)(j0 + r) * (Hn / 2) + kw0 + c4 * 4;
        *(uint4*)&WHw[r * ROWW + c4 * 4] = *(const uint4*)&g_WHt[ga];
        *(uint4*)&WLw[r * ROWW + c4 * 4] = *(const uint4*)&g_WLt[ga];
    }

    // ---- epilogue ownership: 4 consecutive j within OWN tile ----
    const int eb = b0 + ks * 8 + (tid >> 5);
    const int ej = j0 + 4 * (tid & 31);
    float hr[4]  = {0.f, 0.f, 0.f, 0.f};
    float sxr[4] = {1.f, 1.f, 1.f, 1.f};
    float sur[4] = {0.45f, 0.15f, 0.45f, 0.15f};
    const float axc[4] = {20.f/1500.f, 0.1f, 20.f/1500.f, 0.1f};
    const float Uc[4]  = {0.45f, 0.15f, 0.45f, 0.15f};

    // ---- mma lane mapping ----
    const int lane  = tid & 31;
    const int warp  = tid >> 5;
    const int wb    = warp & 1;          // b 32-tile within block
    const int wj    = warp >> 1;         // j 32-tile within block
    const int group = lane >> 2;
    const int tig   = lane & 3;

    __syncthreads();

    for (int t = 0; t < Tn; t++) {
        const int p = t & 1;

        // ---- prefetch dn for this step's epilogue elements ----
        const size_t ti = ((size_t)t * Bn + eb) * Hn + ej;
        float4 dn4 = __ldcs((const float4*)&g_dn[ti]);

        // ---- wait: hp inputs ready (epilogues of grp_hp at step t-1) ----
        if (tid == 0 && t > 0)
            while (ld_acq(&g_cnt_epi[grp_hp]) < 8u * t) { }
        __syncthreads();

        // ---- stage hp hi/lo slice via cp.async ----
        for (int i = tid; i < TB * (KS / 8); i += NT) {   // 64 rows x 16 float4
            int r = i >> 4, c4 = i & 15;
            size_t ga = (size_t)(b0 + r) * (Hn / 2) + kw0 + c4 * 4;
            unsigned so = (unsigned)((r * ROWW + c4 * 4) * 4);
            cpa16(sHH + so, &g_hpHu[p][ga]);
            cpa16(sHL + so, &g_hpLu[p][ga]);
        }
        asm volatile("cp.async.commit_group;" ::: "memory");
        asm volatile("cp.async.wait_group 0;" ::: "memory");
        __syncthreads();

        // ---- tensor GEMM: warp tile 32b x 32j, K=128, 3-product bf16 split ----
        float acc[2][4][4];
        #pragma unroll
        for (int mi = 0; mi < 2; mi++)
            #pragma unroll
            for (int ni = 0; ni < 4; ni++)
                #pragma unroll
                for (int c = 0; c < 4; c++) acc[mi][ni][c] = 0.f;

        #pragma unroll 2
        for (int kt = 0; kt < KS / 16; kt++) {
            const int kw = kt * 8 + tig;
            unsigned ah[2][4], al[2][4];
            #pragma unroll
            for (int mi = 0; mi < 2; mi++) {
                int r0 = (wb * 32 + mi * 16 + group) * ROWW;
                int r1 = r0 + 8 * ROWW;
                ah[mi][0] = HHw[r0 + kw];     ah[mi][1] = HHw[r1 + kw];
                ah[mi][2] = HHw[r0 + kw + 4]; ah[mi][3] = HHw[r1 + kw + 4];
                al[mi][0] = HLw[r0 + kw];     al[mi][1] = HLw[r1 + kw];
                al[mi][2] = HLw[r0 + kw + 4]; al[mi][3] = HLw[r1 + kw + 4];
            }
            unsigned bh[4][2], bl[4][2];
            #pragma unroll
            for (int ni = 0; ni < 4; ni++) {
                int jr = (wj * 32 + ni * 8 + group) * ROWW;
                bh[ni][0] = WHw[jr + kw]; bh[ni][1] = WHw[jr + kw + 4];
                bl[ni][0] = WLw[jr + kw]; bl[ni][1] = WLw[jr + kw + 4];
            }
            #pragma unroll
            for (int mi = 0; mi < 2; mi++)
                #pragma unroll
                for (int ni = 0; ni < 4; ni++) {
                    MMA_BF16(acc[mi][ni], ah[mi], bh[ni]);
                    MMA_BF16(acc[mi][ni], ah[mi], bl[ni]);
                    MMA_BF16(acc[mi][ni], al[mi], bh[ni]);
                }
        }

        // ---- WAR wait on partial slot (2 steps old: normally already done) ----
        if (tid == 0 && t >= 2)
            while (ld_acq(&g_cnt_epi[grp_own]) < 8u * (t - 1)) { }
        __syncthreads();

        // ---- store partials ----
        {
            float* gp = g_part[p][ks];
            const int rb = b0 + wb * 32 + group;
            const int jc = j0 + wj * 32 + tig * 2;
            #pragma unroll
            for (int mi = 0; mi < 2; mi++)
                #pragma unroll
                for (int ni = 0; ni < 4; ni++) {
                    int r = rb + mi * 16;
                    int jj = jc + ni * 8;
                    *(float2*)&gp[(size_t)r * Hn + jj] =
                        make_float2(acc[mi][ni][0], acc[mi][ni][1]);
                    *(float2*)&gp[(size_t)(r + 8) * Hn + jj] =
                        make_float2(acc[mi][ni][2], acc[mi][ni][3]);
                }
        }

        __syncthreads();
        if (tid == 0) {
            red_rel(&g_cnt_part[grp_own]);
            while (ld_acq(&g_cnt_part[grp_own]) < 8u * (t + 1)) { }
        }
        __syncthreads();

        // ---- epilogue over own tile's elements ----
        {
            const size_t pi = (size_t)eb * Hn + ej;
            float4 r = __ldcg((const float4*)&g_part[p][0][pi]);
            #pragma unroll
            for (int s = 1; s < KSPLIT; s++) {
                float4 q = __ldcg((const float4*)&g_part[p][s][pi]);
                r.x += q.x; r.y += q.y; r.z += q.z; r.w += q.w;
            }
            float rv[4] = {r.x, r.y, r.z, r.w};
            float dv[4] = {dn4.x, dn4.y, dn4.z, dn4.w};
            float hn[4];
            unsigned hpH[4], hpL[4];
            #pragma unroll
            for (int u = 0; u < 4; u++) {
                float h = fmaxf(0.8f * hr[u] + dv[u] + rv[u], 0.f);
                hn[u] = h;
                float sx = sxr[u], su = sur[u];
                float ax = axc[u], U = Uc[u];
                float sxn = sx + ax * (1.f - sx) - 0.02f * su * sx * h;
                sxn = fminf(fmaxf(sxn, 0.f), 1.f);
                float sun = su + ax * (U - su) + 0.02f * U * (1.f - su) * h;
                sun = fminf(fmaxf(sun, 0.f), 1.f);
                hr[u] = h; sxr[u] = sxn; sur[u] = sun;
                float hp = sun * sxn * h;
                __nv_bfloat16 hi = __float2bfloat16_rn(hp);
                __nv_bfloat16 lo = __float2bfloat16_rn(hp - __bfloat162float(hi));
                hpH[u] = (unsigned)__bfloat16_as_ushort(hi);
                hpL[u] = (unsigned)__bfloat16_as_ushort(lo);
            }
            const size_t hw = ((size_t)eb * Hn + ej) >> 1;
            g_hpHu[p ^ 1][hw]     = hpH[0] | (hpH[1] << 16);
            g_hpHu[p ^ 1][hw + 1] = hpH[2] | (hpH[3] << 16);
            g_hpLu[p ^ 1][hw]     = hpL[0] | (hpL[1] << 16);
            g_hpLu[p ^ 1][hw + 1] = hpL[2] | (hpL[3] << 16);

            __stcs((float4*)&acts[((size_t)eb * Tn + t) * Hn + ej],
                   make_float4(hn[0], hn[1], hn[2], hn[3]));
        }

        __syncthreads();
        if (tid == 0) red_rel(&g_cnt_epi[grp_own]);
    }
}

// ---------------------------------------------------------------------------
__global__ __launch_bounds__(128) void head_kernel(
    const float* __restrict__ acts, const float* __restrict__ w_out,
    const float* __restrict__ b_out, const float* __restrict__ c1_w,
    const float* __restrict__ c1_b, const float* __restrict__ c2_w,
    const float* __restrict__ c2_b, float* __restrict__ outputs,
    float* __restrict__ p)
{
    const int t = blockIdx.x, b = blockIdx.y;
    const int tid = threadIdx.x;
    float s[9] = {};
    const float* arow = acts + ((size_t)b * Tn + t) * Hn;
    for (int h = tid; h < Hn; h += 128) {
        float a = arow[h];
        #pragma unroll
        for (int o = 0; o < 3; o++) s[o] = fmaf(a, w_out[o * Hn + h], s[o]);
        #pragma unroll
        for (int m = 0; m < 6; m++) s[3 + m] = fmaf(a, c1_w[m * Hn + h], s[3 + m]);
    }
    __shared__ float red[9][128];
    #pragma unroll
    for (int q = 0; q < 9; q++) red[q][tid] = s[q];
    __syncthreads();
    for (int st = 64; st > 0; st >>= 1) {
        if (tid < st) {
            #pragma unroll
            for (int q = 0; q < 9; q++) red[q][tid] += red[q][tid + st];
        }
        __syncthreads();
    }
    if (tid == 0) {
        size_t ob = ((size_t)b * Tn + t) * 3;
        #pragma unroll
        for (int o = 0; o < 3; o++) outputs[ob + o] = red[o][0] + b_out[o];
        float z[6];
        #pragma unroll
        for (int m = 0; m < 6; m++) z[m] = red[3 + m][0] + c1_b[m];
        size_t pb = ((size_t)b * Tn + t) * 24;
        #pragma unroll
        for (int j = 0; j < 3; j++)
            #pragma unroll
            for (int o = 0; o < 8; o++)
                p[pb + j * 8 + o] = c2_b[j * 8 + o]
                                  + z[j * 2 + 0] * c2_w[j * 16 + o * 2 + 0]
                                  + z[j * 2 + 1] * c2_w[j * 16 + o * 2 + 1];
    }
}

// ---------------------------------------------------------------------------
extern "C" void kernel_launch(void* const* d_in, const int* in_sizes, int n_in,
                              void* d_out, int out_size)
{
    (void)in_sizes; (void)n_in; (void)out_size;
    const float* stim  = (const float*)d_in[0];
    const float* ctx   = (const float*)d_in[1];
    const float* w_rec = (const float*)d_in[2];
    const float* b_rec = (const float*)d_in[3];
    const float* w_in  = (const float*)d_in[4];
    const float* w_ctx = (const float*)d_in[5];
    const float* w_out = (const float*)d_in[6];
    const float* b_out = (const float*)d_in[7];
    const float* c1_w  = (const float*)d_in[8];
    const float* c1_b  = (const float*)d_in[9];
    const float* c2_w  = (const float*)d_in[10];
    const float* c2_b  = (const float*)d_in[11];
    const float* noise = (const float*)d_in[12];

    float* out      = (float*)d_out;
    float* outputs  = out;                              // [B,T,3]
    float* acts     = out + (size_t)Bn * Tn * 3;        // [B,T,H]
    float* p        = acts + (size_t)Bn * Tn * Hn;      // [B,T,3,8]

    const int smem_bytes = (2 * TJ * ROWW + 2 * TB * ROWW) * (int)sizeof(unsigned);
    static bool attr_set = false;
    if (!attr_set) {
        cudaFuncSetAttribute(rnn_persistent,
                             cudaFuncAttributeMaxDynamicSharedMemorySize,
                             smem_bytes);
        attr_set = true;
    }

    prep_W<<<(Hn * Hn) / 256, 256>>>(w_rec);
    init_state<<<(Bn * Hn) / 256, 256>>>();
    drive_kernel<<<dim3(Tn, Hn / 64, Bn / 64), 256>>>(stim, ctx, w_in, w_ctx,
                                                      b_rec, noise);

    rnn_persistent<<<NB, NT, smem_bytes>>>(acts);

    head_kernel<<<dim3(Tn, Bn), 128>>>(acts, w_out, b_out, c1_w, c1_b,
                                       c2_w, c2_b, outputs, p);
}